// round 1
// baseline (speedup 1.0000x reference)
#include <cuda_runtime.h>
#include <stdint.h>

#define N_NODES 100000
#define N_EDGES 1600000
#define F_IN  64
#define F_HID 64
#define F_OUT 32

// ---------------- static device scratch (no allocation allowed) ----------------
__device__ float g_deg [N_NODES];
__device__ float g_dinv[N_NODES];
__device__ float g_xws [N_NODES * F_HID];   // (x@W1)*dinv
__device__ float g_S1  [N_NODES * F_HID];   // scatter sum layer 1
__device__ float g_h   [N_NODES * F_HID];   // relu hidden
__device__ float g_hws [N_NODES * F_OUT];   // (h@W2)*dinv
__device__ float g_S2  [N_NODES * F_OUT];   // scatter sum layer 2
__device__ int   g_is64;

// ---------------- edge index fetch (int64 vs int32 runtime layout) -------------
__device__ __forceinline__ void get_edge(const int* __restrict__ w, int is64,
                                         int e, int& s, int& d) {
    if (is64) {
        // int64 array: src[e] low word at 2e; dst array starts at word 2*E
        s = w[2 * e];
        d = w[2 * N_EDGES + 2 * e];
    } else {
        s = w[e];
        d = w[N_EDGES + e];
    }
}

// detect dtype: values < 100000 -> if int64, every odd 32-bit word is 0
__global__ void k_detect(const int* __restrict__ w) {
    int ok = 1;
    for (int i = 0; i < 512; i++)
        if (w[2 * i + 1] != 0) { ok = 0; break; }
    g_is64 = ok;
}

// ---------------- zero scratch ----------------
__global__ void k_zero() {
    int i = blockIdx.x * blockDim.x + threadIdx.x;
    if (i < N_NODES * F_HID) g_S1[i] = 0.0f;
    if (i < N_NODES * F_OUT) g_S2[i] = 0.0f;
    if (i < N_NODES)         g_deg[i] = 0.0f;
}

// ---------------- degree ----------------
__global__ void k_deg(const int* __restrict__ ew) {
    int e = blockIdx.x * blockDim.x + threadIdx.x;
    if (e >= N_EDGES) return;
    int s, d;
    get_edge(ew, g_is64, e, s, d);
    atomicAdd(&g_deg[d], 1.0f);
}

__global__ void k_dinv() {
    int i = blockIdx.x * blockDim.x + threadIdx.x;
    if (i >= N_NODES) return;
    g_dinv[i] = rsqrtf(g_deg[i] + 1.0f);
}

// ---------------- GEMM1: xws = (x @ W1) * dinv ----------------
// one thread per row, W1 in shared, 64 fp32 accumulators
__global__ void __launch_bounds__(256) k_gemm1(const float* __restrict__ x,
                                               const float* __restrict__ W) {
    __shared__ float4 ws[F_IN * (F_HID / 4)];  // 64 x 16 float4 = 16KB
    int tid = threadIdx.x;
    for (int i = tid; i < F_IN * (F_HID / 4); i += 256)
        ws[i] = ((const float4*)W)[i];
    __syncthreads();

    int row = blockIdx.x * 256 + tid;
    if (row >= N_NODES) return;

    float4 acc[16];
#pragma unroll
    for (int j = 0; j < 16; j++) acc[j] = make_float4(0.f, 0.f, 0.f, 0.f);

    const float4* xr = (const float4*)(x + (size_t)row * F_IN);
#pragma unroll
    for (int kk = 0; kk < 16; kk++) {
        float4 xv = __ldg(xr + kk);
        float xs[4] = {xv.x, xv.y, xv.z, xv.w};
#pragma unroll
        for (int t = 0; t < 4; t++) {
            int k = kk * 4 + t;
            float xk = xs[t];
#pragma unroll
            for (int j = 0; j < 16; j++) {
                float4 w4 = ws[k * 16 + j];
                acc[j].x = fmaf(xk, w4.x, acc[j].x);
                acc[j].y = fmaf(xk, w4.y, acc[j].y);
                acc[j].z = fmaf(xk, w4.z, acc[j].z);
                acc[j].w = fmaf(xk, w4.w, acc[j].w);
            }
        }
    }
    float s = g_dinv[row];
    float4* o = (float4*)(g_xws + (size_t)row * F_HID);
#pragma unroll
    for (int j = 0; j < 16; j++) {
        float4 a = acc[j];
        a.x *= s; a.y *= s; a.z *= s; a.w *= s;
        o[j] = a;
    }
}

// ---------------- scatter layer 1: S1[dst] += xws[src]  (16 float4 per edge) ----
__global__ void __launch_bounds__(256) k_scatter1(const int* __restrict__ ew) {
    int gid = blockIdx.x * blockDim.x + threadIdx.x;
    if (gid >= N_EDGES * 16) return;
    int e = gid >> 4;
    int c = gid & 15;
    int s, d;
    get_edge(ew, g_is64, e, s, d);
    float4 v = __ldg((const float4*)(g_xws + (size_t)s * F_HID) + c);
    float* p = g_S1 + (size_t)d * F_HID + c * 4;
    asm volatile("red.global.add.v4.f32 [%0], {%1,%2,%3,%4};"
                 :: "l"(p), "f"(v.x), "f"(v.y), "f"(v.z), "f"(v.w) : "memory");
}

// ---------------- hidden: h = relu(dinv*(S1 + xws) + b1) ----------------
__global__ void k_hidden(const float* __restrict__ b1) {
    int i4 = blockIdx.x * blockDim.x + threadIdx.x;
    if (i4 >= N_NODES * (F_HID / 4)) return;
    int row = i4 >> 4;          // /16
    int j4  = i4 & 15;
    float s = g_dinv[row];
    float4 a = ((const float4*)g_S1)[i4];
    float4 w = ((const float4*)g_xws)[i4];
    float4 b = ((const float4*)b1)[j4];
    float4 r;
    r.x = fmaxf(s * (a.x + w.x) + b.x, 0.f);
    r.y = fmaxf(s * (a.y + w.y) + b.y, 0.f);
    r.z = fmaxf(s * (a.z + w.z) + b.z, 0.f);
    r.w = fmaxf(s * (a.w + w.w) + b.w, 0.f);
    ((float4*)g_h)[i4] = r;
}

// ---------------- GEMM2: hws = (h @ W2) * dinv ----------------
__global__ void __launch_bounds__(256) k_gemm2(const float* __restrict__ W) {
    __shared__ float4 ws[F_HID * (F_OUT / 4)];  // 64 x 8 float4 = 8KB
    int tid = threadIdx.x;
    for (int i = tid; i < F_HID * (F_OUT / 4); i += 256)
        ws[i] = ((const float4*)W)[i];
    __syncthreads();

    int row = blockIdx.x * 256 + tid;
    if (row >= N_NODES) return;

    float4 acc[8];
#pragma unroll
    for (int j = 0; j < 8; j++) acc[j] = make_float4(0.f, 0.f, 0.f, 0.f);

    const float4* hr = (const float4*)(g_h + (size_t)row * F_HID);
#pragma unroll
    for (int kk = 0; kk < 16; kk++) {
        float4 hv = __ldg(hr + kk);
        float hs[4] = {hv.x, hv.y, hv.z, hv.w};
#pragma unroll
        for (int t = 0; t < 4; t++) {
            int k = kk * 4 + t;
            float hk = hs[t];
#pragma unroll
            for (int j = 0; j < 8; j++) {
                float4 w4 = ws[k * 8 + j];
                acc[j].x = fmaf(hk, w4.x, acc[j].x);
                acc[j].y = fmaf(hk, w4.y, acc[j].y);
                acc[j].z = fmaf(hk, w4.z, acc[j].z);
                acc[j].w = fmaf(hk, w4.w, acc[j].w);
            }
        }
    }
    float s = g_dinv[row];
    float4* o = (float4*)(g_hws + (size_t)row * F_OUT);
#pragma unroll
    for (int j = 0; j < 8; j++) {
        float4 a = acc[j];
        a.x *= s; a.y *= s; a.z *= s; a.w *= s;
        o[j] = a;
    }
}

// ---------------- scatter layer 2: S2[dst] += hws[src]  (8 float4 per edge) ----
__global__ void __launch_bounds__(256) k_scatter2(const int* __restrict__ ew) {
    int gid = blockIdx.x * blockDim.x + threadIdx.x;
    if (gid >= N_EDGES * 8) return;
    int e = gid >> 3;
    int c = gid & 7;
    int s, d;
    get_edge(ew, g_is64, e, s, d);
    float4 v = __ldg((const float4*)(g_hws + (size_t)s * F_OUT) + c);
    float* p = g_S2 + (size_t)d * F_OUT + c * 4;
    asm volatile("red.global.add.v4.f32 [%0], {%1,%2,%3,%4};"
                 :: "l"(p), "f"(v.x), "f"(v.y), "f"(v.z), "f"(v.w) : "memory");
}

// ---------------- output: out = dinv*(S2 + hws) + b2 ----------------
__global__ void k_out(const float* __restrict__ b2, float* __restrict__ out) {
    int i4 = blockIdx.x * blockDim.x + threadIdx.x;
    if (i4 >= N_NODES * (F_OUT / 4)) return;
    int row = i4 >> 3;          // /8
    int j4  = i4 & 7;
    float s = g_dinv[row];
    float4 a = ((const float4*)g_S2)[i4];
    float4 w = ((const float4*)g_hws)[i4];
    float4 b = ((const float4*)b2)[j4];
    float4 r;
    r.x = s * (a.x + w.x) + b.x;
    r.y = s * (a.y + w.y) + b.y;
    r.z = s * (a.z + w.z) + b.z;
    r.w = s * (a.w + w.w) + b.w;
    ((float4*)out)[i4] = r;
}

// ---------------- launch ----------------
extern "C" void kernel_launch(void* const* d_in, const int* in_sizes, int n_in,
                              void* d_out, int out_size) {
    const float* x  = (const float*)d_in[0];
    const int*   ew = (const int*)d_in[1];   // edge_index, int32 or int64 (detected)
    const float* W1 = (const float*)d_in[2];
    const float* b1 = (const float*)d_in[3];
    const float* W2 = (const float*)d_in[4];
    const float* b2 = (const float*)d_in[5];
    float* out = (float*)d_out;

    const int T = 256;

    k_detect<<<1, 1>>>(ew);
    k_zero<<<(N_NODES * F_HID + T - 1) / T, T>>>();
    k_deg<<<(N_EDGES + T - 1) / T, T>>>(ew);
    k_dinv<<<(N_NODES + T - 1) / T, T>>>();

    k_gemm1<<<(N_NODES + T - 1) / T, T>>>(x, W1);
    k_scatter1<<<(N_EDGES * 16 + T - 1) / T, T>>>(ew);
    k_hidden<<<(N_NODES * (F_HID / 4) + T - 1) / T, T>>>(b1);

    k_gemm2<<<(N_NODES + T - 1) / T, T>>>(W2);
    k_scatter2<<<(N_EDGES * 8 + T - 1) / T, T>>>(ew);
    k_out<<<(N_NODES * (F_OUT / 4) + T - 1) / T, T>>>(b2, out);
}